// round 4
// baseline (speedup 1.0000x reference)
#include <cuda_runtime.h>
#include <cuda_bf16.h>

#define MAX_STEPS 20
#define THRESHOLD 0.99f

// ---------------------------------------------------------------------------
// Scalar ACT recursion (mirrors the reference scan exactly, per row).
// p = sigmoid(x.W + b) is constant across the 20 steps, so the state
// recursion collapses to state = m * x with m from this scalar loop.
// ---------------------------------------------------------------------------
__device__ __forceinline__ void act_scalar(float p, float& m, float& ponder) {
    float hp = 0.0f, rem = 0.0f, nup = 0.0f;
    m = 0.0f;
#pragma unroll
    for (int s = 0; s < MAX_STEPS; s++) {
        float still = (hp < 1.0f) ? 1.0f : 0.0f;
        float hpn = hp + p * still;
        float nh = (hpn > THRESHOLD) ? still : 0.0f;   // new_halted
        hp = hpn;
        rem = rem + nh * (1.0f - hp);
        hp = hp + nh * rem;                             // exact 1.0 on halt
        float w = p * still + nh * rem;                 // update_weights
        m = (1.0f - w) * m + w;
        nup += still;
    }
    ponder = nup + rem;
}

__device__ __forceinline__ void stcs_f4(float4* p, float4 v) {
    // streaming store: state is write-once, evict-first in L2
    asm volatile("st.global.cs.v4.f32 [%0], {%1,%2,%3,%4};"
                 :: "l"(p), "f"(v.x), "f"(v.y), "f"(v.z), "f"(v.w)
                 : "memory");
}

// ---------------------------------------------------------------------------
// D == 1024 specialization: TWO warps per row (4 rows / 256-thread block).
// Each lane holds 4 float4 of the row in registers (x read exactly once,
// reused for writeback). Lower reg pressure (-> higher occupancy) and
// shallower per-warp LDG batches (-> less L1tex queue contention) than the
// one-warp-per-row version. W staged in shared memory.
// ---------------------------------------------------------------------------
__global__ __launch_bounds__(256, 6)
void act_kernel_d1024(const float* __restrict__ x,
                      const float* __restrict__ W,
                      const float* __restrict__ b,
                      float* __restrict__ state,
                      float* __restrict__ ponder,
                      int rows, int write_ponder)
{
    __shared__ float4 sW[256];      // 1024 floats of W
    __shared__ float  sDot[8];      // one partial dot per warp
    const int tid = threadIdx.x;
    sW[tid] = reinterpret_cast<const float4*>(W)[tid];

    const int warp = tid >> 5;      // 0..7
    const int lane = tid & 31;
    const int row_in_blk = warp >> 1;   // 0..3
    const int half = warp & 1;          // which half of the row
    const long long row = (long long)blockIdx.x * 4 + row_in_blk;
    const bool valid = (row < rows);

    __syncthreads();                // sW ready

    float4 v[4];
    float dot = 0.0f;
    const float4* xr = reinterpret_cast<const float4*>(x) + row * 256;
    if (valid) {
#pragma unroll
        for (int c = 0; c < 4; c++) {
            const int i = half * 128 + lane + 32 * c;   // float4 index in row
            v[c] = __ldg(&xr[i]);
            const float4 w = sW[i];
            dot = fmaf(v[c].x, w.x, dot);
            dot = fmaf(v[c].y, w.y, dot);
            dot = fmaf(v[c].z, w.z, dot);
            dot = fmaf(v[c].w, w.w, dot);
        }
    }
#pragma unroll
    for (int o = 16; o; o >>= 1)
        dot += __shfl_xor_sync(0xffffffffu, dot, o);
    if (lane == 0) sDot[warp] = dot;
    __syncthreads();

    if (!valid) return;

    const float full_dot = sDot[warp] + sDot[warp ^ 1];
    const float z = full_dot + b[0];
    const float p = 1.0f / (1.0f + expf(-z));

    float m, pt;
    act_scalar(p, m, pt);

    float4* sr = reinterpret_cast<float4*>(state) + row * 256;
#pragma unroll
    for (int c = 0; c < 4; c++) {
        const int i = half * 128 + lane + 32 * c;
        float4 o;
        o.x = m * v[c].x; o.y = m * v[c].y;
        o.z = m * v[c].z; o.w = m * v[c].w;
        stcs_f4(&sr[i], o);
    }
    if (half == 0 && lane == 0 && write_ponder) ponder[row] = pt;
}

// ---------------------------------------------------------------------------
// Generic fallback (any D): one block per row, two-pass over x.
// ---------------------------------------------------------------------------
__global__ __launch_bounds__(256)
void act_kernel_generic(const float* __restrict__ x,
                        const float* __restrict__ W,
                        const float* __restrict__ b,
                        float* __restrict__ state,
                        float* __restrict__ ponder,
                        int rows, int D, int write_ponder)
{
    __shared__ float red[8];
    __shared__ float s_m;
    const int row = blockIdx.x;
    if (row >= rows) return;
    const int tid = threadIdx.x;
    const float* xr = x + (long long)row * D;

    float dot = 0.0f;
    for (int i = tid; i < D; i += blockDim.x)
        dot = fmaf(xr[i], W[i], dot);
#pragma unroll
    for (int o = 16; o; o >>= 1)
        dot += __shfl_xor_sync(0xffffffffu, dot, o);
    if ((tid & 31) == 0) red[tid >> 5] = dot;
    __syncthreads();
    if (tid == 0) {
        float d = 0.0f;
        for (int wi = 0; wi < (int)(blockDim.x >> 5); wi++) d += red[wi];
        const float z = d + b[0];
        const float p = 1.0f / (1.0f + expf(-z));
        float m, pt;
        act_scalar(p, m, pt);
        s_m = m;
        if (write_ponder) ponder[row] = pt;
    }
    __syncthreads();
    const float m = s_m;
    float* sr = state + (long long)row * D;
    for (int i = tid; i < D; i += blockDim.x)
        sr[i] = m * xr[i];
}

extern "C" void kernel_launch(void* const* d_in, const int* in_sizes, int n_in,
                              void* d_out, int out_size)
{
    const float* x = (const float*)d_in[0];
    const float* W = (const float*)d_in[1];
    const float* b = (const float*)d_in[2];

    const int D = in_sizes[1];                 // W is (D, 1)
    const int rows = in_sizes[0] / D;          // B*S

    float* out = (float*)d_out;
    float* state = out;
    float* ponder = out + (long long)rows * D;
    const int write_ponder =
        ((long long)out_size >= (long long)rows * D + rows) ? 1 : 0;

    if (D == 1024) {
        const int blocks = (rows + 3) / 4;     // 4 rows per 256-thread block
        act_kernel_d1024<<<blocks, 256>>>(x, W, b, state, ponder, rows,
                                          write_ponder);
    } else {
        act_kernel_generic<<<rows, 256>>>(x, W, b, state, ponder, rows, D,
                                          write_ponder);
    }
}

// round 6
// speedup vs baseline: 1.0007x; 1.0007x over previous
#include <cuda_runtime.h>
#include <cuda_bf16.h>

#define MAX_STEPS 20
#define THRESHOLD 0.99f

// ---------------------------------------------------------------------------
// Scalar ACT recursion (mirrors the reference scan exactly, per row).
// p = sigmoid(x.W + b) is constant across the 20 steps, so the state
// recursion collapses to state = m * x with m from this scalar loop.
//
// Early exit: once a row halts, hp == 1.0 EXACTLY (hp + (1-hp) with 1-hp
// exact by Sterbenz for hp in [0.5,2]), so still=0 freezes every carry
// bitwise. Breaking on hp >= 1.0 is therefore identical to running the
// remaining masked iterations. All lanes of a warp share p -> the branch
// is warp-uniform (no divergence). Typical iteration count: 2-5 of 20.
// ---------------------------------------------------------------------------
__device__ __forceinline__ void act_scalar(float p, float& m, float& ponder) {
    float hp = 0.0f, rem = 0.0f, nup = 0.0f;
    m = 0.0f;
    for (int s = 0; s < MAX_STEPS; s++) {
        float still = (hp < 1.0f) ? 1.0f : 0.0f;
        float hpn = hp + p * still;
        float nh = (hpn > THRESHOLD) ? still : 0.0f;   // new_halted
        hp = hpn;
        rem = rem + nh * (1.0f - hp);
        hp = hp + nh * rem;                             // exact 1.0 on halt
        float w = p * still + nh * rem;                 // update_weights
        m = (1.0f - w) * m + w;
        nup += still;
        if (hp >= 1.0f) break;       // frozen from here on (bitwise exact)
    }
    ponder = nup + rem;
}

__device__ __forceinline__ void stcs_f4(float4* p, float4 v) {
    // streaming store: state is write-once, evict-first in L2
    asm volatile("st.global.cs.v4.f32 [%0], {%1,%2,%3,%4};"
                 :: "l"(p), "f"(v.x), "f"(v.y), "f"(v.z), "f"(v.w)
                 : "memory");
}

// ---------------------------------------------------------------------------
// D == 1024 specialization: one warp per row, x held in registers
// (8 float4 per lane), read once / write once. W staged in shared memory.
// (R2-measured best memory throughput: 5553 GB/s.)
// ---------------------------------------------------------------------------
__global__ __launch_bounds__(256, 4)
void act_kernel_d1024(const float* __restrict__ x,
                      const float* __restrict__ W,
                      const float* __restrict__ b,
                      float* __restrict__ state,
                      float* __restrict__ ponder,
                      int rows, int write_ponder)
{
    __shared__ float4 sW[256];   // 1024 floats of W
    const int tid = threadIdx.x;
    sW[tid] = reinterpret_cast<const float4*>(W)[tid];
    __syncthreads();

    const int warp = tid >> 5;
    const int lane = tid & 31;
    const long long row = (long long)blockIdx.x * 8 + warp;
    if (row >= rows) return;

    const float4* xr = reinterpret_cast<const float4*>(x) + row * 256;

    float4 v[8];
    float dot = 0.0f;
#pragma unroll
    for (int c = 0; c < 8; c++) {
        const int i = lane + 32 * c;
        v[c] = __ldg(&xr[i]);
        const float4 w = sW[i];
        dot = fmaf(v[c].x, w.x, dot);
        dot = fmaf(v[c].y, w.y, dot);
        dot = fmaf(v[c].z, w.z, dot);
        dot = fmaf(v[c].w, w.w, dot);
    }
#pragma unroll
    for (int o = 16; o; o >>= 1)
        dot += __shfl_xor_sync(0xffffffffu, dot, o);

    const float z = dot + b[0];
    const float p = 1.0f / (1.0f + expf(-z));

    float m, pt;
    act_scalar(p, m, pt);

    float4* sr = reinterpret_cast<float4*>(state) + row * 256;
#pragma unroll
    for (int c = 0; c < 8; c++) {
        const int i = lane + 32 * c;
        float4 o;
        o.x = m * v[c].x; o.y = m * v[c].y;
        o.z = m * v[c].z; o.w = m * v[c].w;
        stcs_f4(&sr[i], o);
    }
    if (lane == 0 && write_ponder) ponder[row] = pt;
}

// ---------------------------------------------------------------------------
// Generic fallback (any D): one block per row, two-pass over x.
// ---------------------------------------------------------------------------
__global__ __launch_bounds__(256)
void act_kernel_generic(const float* __restrict__ x,
                        const float* __restrict__ W,
                        const float* __restrict__ b,
                        float* __restrict__ state,
                        float* __restrict__ ponder,
                        int rows, int D, int write_ponder)
{
    __shared__ float red[8];
    __shared__ float s_m;
    const int row = blockIdx.x;
    if (row >= rows) return;
    const int tid = threadIdx.x;
    const float* xr = x + (long long)row * D;

    float dot = 0.0f;
    for (int i = tid; i < D; i += blockDim.x)
        dot = fmaf(xr[i], W[i], dot);
#pragma unroll
    for (int o = 16; o; o >>= 1)
        dot += __shfl_xor_sync(0xffffffffu, dot, o);
    if ((tid & 31) == 0) red[tid >> 5] = dot;
    __syncthreads();
    if (tid == 0) {
        float d = 0.0f;
        for (int wi = 0; wi < (int)(blockDim.x >> 5); wi++) d += red[wi];
        const float z = d + b[0];
        const float p = 1.0f / (1.0f + expf(-z));
        float m, pt;
        act_scalar(p, m, pt);
        s_m = m;
        if (write_ponder) ponder[row] = pt;
    }
    __syncthreads();
    const float m = s_m;
    float* sr = state + (long long)row * D;
    for (int i = tid; i < D; i += blockDim.x)
        sr[i] = m * xr[i];
}

extern "C" void kernel_launch(void* const* d_in, const int* in_sizes, int n_in,
                              void* d_out, int out_size)
{
    const float* x = (const float*)d_in[0];
    const float* W = (const float*)d_in[1];
    const float* b = (const float*)d_in[2];

    const int D = in_sizes[1];                 // W is (D, 1)
    const int rows = in_sizes[0] / D;          // B*S

    float* out = (float*)d_out;
    float* state = out;
    float* ponder = out + (long long)rows * D;
    const int write_ponder =
        ((long long)out_size >= (long long)rows * D + rows) ? 1 : 0;

    if (D == 1024) {
        const int blocks = (rows + 7) / 8;     // 8 warps (rows) per block
        act_kernel_d1024<<<blocks, 256>>>(x, W, b, state, ponder, rows,
                                          write_ponder);
    } else {
        act_kernel_generic<<<rows, 256>>>(x, W, b, state, ponder, rows, D,
                                          write_ponder);
    }
}

// round 7
// speedup vs baseline: 1.0070x; 1.0063x over previous
#include <cuda_runtime.h>
#include <cuda_bf16.h>

#define MAX_STEPS 20
#define THRESHOLD 0.99f

// ---------------------------------------------------------------------------
// Scalar ACT recursion (mirrors the reference scan exactly, per row).
// p = sigmoid(x.W + b) is constant across the 20 steps, so the state
// recursion collapses to state = m * x with m from this scalar loop.
//
// Early exit: once a row halts, hp == 1.0 EXACTLY (hp + (1-hp) with 1-hp
// exact by Sterbenz for hp in [0.5,2]), so still=0 freezes every carry
// bitwise; breaking on hp >= 1.0 is identical to running the remaining
// masked iterations. All lanes of a warp share p -> warp-uniform branch.
// ---------------------------------------------------------------------------
__device__ __forceinline__ void act_scalar(float p, float& m, float& ponder) {
    float hp = 0.0f, rem = 0.0f, nup = 0.0f;
    m = 0.0f;
    for (int s = 0; s < MAX_STEPS; s++) {
        float still = (hp < 1.0f) ? 1.0f : 0.0f;
        float hpn = hp + p * still;
        float nh = (hpn > THRESHOLD) ? still : 0.0f;   // new_halted
        hp = hpn;
        rem = rem + nh * (1.0f - hp);
        hp = hp + nh * rem;                             // exact 1.0 on halt
        float w = p * still + nh * rem;                 // update_weights
        m = (1.0f - w) * m + w;
        nup += still;
        if (hp >= 1.0f) break;       // frozen from here on (bitwise exact)
    }
    ponder = nup + rem;
}

__device__ __forceinline__ void stcs_f4(float4* p, float4 v) {
    // streaming store: state is write-once, evict-first in L2
    asm volatile("st.global.cs.v4.f32 [%0], {%1,%2,%3,%4};"
                 :: "l"(p), "f"(v.x), "f"(v.y), "f"(v.z), "f"(v.w)
                 : "memory");
}

// Pair-scoped barrier: synchronize exactly the two warps of one row.
// Avoids the block-wide __syncthreads convoy (all 8 warps' stores gated on
// the slowest warp's loads) that confounded the R4 measurement.
__device__ __forceinline__ void bar_pair(int pair_id) {
    asm volatile("bar.sync %0, 64;" :: "r"(pair_id + 1) : "memory");
}

// ---------------------------------------------------------------------------
// D == 1024: TWO warps per row (4 rows / 256-thread block). Each lane holds
// 4 float4 (regs ~40 -> 6 CTAs/SM, occ ~67%). x read once into regs, reused
// for writeback. Cross-warp dot combine via smem + pair-scoped named barrier.
// ---------------------------------------------------------------------------
__global__ __launch_bounds__(256, 6)
void act_kernel_d1024(const float* __restrict__ x,
                      const float* __restrict__ W,
                      const float* __restrict__ b,
                      float* __restrict__ state,
                      float* __restrict__ ponder,
                      int rows, int write_ponder)
{
    __shared__ float4 sW[256];            // 1024 floats of W
    __shared__ volatile float sDot[8];    // one partial dot per warp
    const int tid = threadIdx.x;
    sW[tid] = reinterpret_cast<const float4*>(W)[tid];

    const int warp = tid >> 5;            // 0..7
    const int lane = tid & 31;
    const int pair = warp >> 1;           // 0..3 (row within block)
    const int half = warp & 1;            // which half of the row
    const long long row = (long long)blockIdx.x * 4 + pair;
    const bool valid = (row < rows);

    __syncthreads();                      // sW ready (one block-wide sync)

    float4 v[4];
    float dot = 0.0f;
    const float4* xr = reinterpret_cast<const float4*>(x) + row * 256;
    if (valid) {
#pragma unroll
        for (int c = 0; c < 4; c++) {
            const int i = half * 128 + lane + 32 * c;   // float4 index in row
            v[c] = __ldg(&xr[i]);
            const float4 w = sW[i];
            dot = fmaf(v[c].x, w.x, dot);
            dot = fmaf(v[c].y, w.y, dot);
            dot = fmaf(v[c].z, w.z, dot);
            dot = fmaf(v[c].w, w.w, dot);
        }
    }
#pragma unroll
    for (int o = 16; o; o >>= 1)
        dot += __shfl_xor_sync(0xffffffffu, dot, o);

    if (!valid) return;                   // pair partner is also invalid

    if (lane == 0) sDot[warp] = dot;
    bar_pair(pair);                       // only this row's two warps sync

    const float full_dot = sDot[warp] + sDot[warp ^ 1];
    const float z = full_dot + b[0];
    const float p = 1.0f / (1.0f + expf(-z));

    float m, pt;
    act_scalar(p, m, pt);

    float4* sr = reinterpret_cast<float4*>(state) + row * 256;
#pragma unroll
    for (int c = 0; c < 4; c++) {
        const int i = half * 128 + lane + 32 * c;
        float4 o;
        o.x = m * v[c].x; o.y = m * v[c].y;
        o.z = m * v[c].z; o.w = m * v[c].w;
        stcs_f4(&sr[i], o);
    }
    if (half == 0 && lane == 0 && write_ponder) ponder[row] = pt;
}

// ---------------------------------------------------------------------------
// Generic fallback (any D): one block per row, two-pass over x.
// ---------------------------------------------------------------------------
__global__ __launch_bounds__(256)
void act_kernel_generic(const float* __restrict__ x,
                        const float* __restrict__ W,
                        const float* __restrict__ b,
                        float* __restrict__ state,
                        float* __restrict__ ponder,
                        int rows, int D, int write_ponder)
{
    __shared__ float red[8];
    __shared__ float s_m;
    const int row = blockIdx.x;
    if (row >= rows) return;
    const int tid = threadIdx.x;
    const float* xr = x + (long long)row * D;

    float dot = 0.0f;
    for (int i = tid; i < D; i += blockDim.x)
        dot = fmaf(xr[i], W[i], dot);
#pragma unroll
    for (int o = 16; o; o >>= 1)
        dot += __shfl_xor_sync(0xffffffffu, dot, o);
    if ((tid & 31) == 0) red[tid >> 5] = dot;
    __syncthreads();
    if (tid == 0) {
        float d = 0.0f;
        for (int wi = 0; wi < (int)(blockDim.x >> 5); wi++) d += red[wi];
        const float z = d + b[0];
        const float p = 1.0f / (1.0f + expf(-z));
        float m, pt;
        act_scalar(p, m, pt);
        s_m = m;
        if (write_ponder) ponder[row] = pt;
    }
    __syncthreads();
    const float m = s_m;
    float* sr = state + (long long)row * D;
    for (int i = tid; i < D; i += blockDim.x)
        sr[i] = m * xr[i];
}

extern "C" void kernel_launch(void* const* d_in, const int* in_sizes, int n_in,
                              void* d_out, int out_size)
{
    const float* x = (const float*)d_in[0];
    const float* W = (const float*)d_in[1];
    const float* b = (const float*)d_in[2];

    const int D = in_sizes[1];                 // W is (D, 1)
    const int rows = in_sizes[0] / D;          // B*S

    float* out = (float*)d_out;
    float* state = out;
    float* ponder = out + (long long)rows * D;
    const int write_ponder =
        ((long long)out_size >= (long long)rows * D + rows) ? 1 : 0;

    if (D == 1024) {
        const int blocks = (rows + 3) / 4;     // 4 rows per 256-thread block
        act_kernel_d1024<<<blocks, 256>>>(x, W, b, state, ponder, rows,
                                          write_ponder);
    } else {
        act_kernel_generic<<<rows, 256>>>(x, W, b, state, ponder, rows, D,
                                          write_ponder);
    }
}